// round 15
// baseline (speedup 1.0000x reference)
#include <cuda_runtime.h>
#include <cuda_bf16.h>
#include <mma.h>
#include <math.h>

#define NSEQ 1024
#define CS   384
#define CZ   128
#define NH   16
#define DH   24
#define HC   384
#define NN   (NSEQ*NSEQ)
#define RSQRT_D 0.2041241452319315f

typedef unsigned long long u64;
typedef unsigned int u32;

__device__ __forceinline__ u64 pk2(float a, float b) {
    u64 r; asm("mov.b64 %0,{%1,%2};" : "=l"(r) : "f"(a), "f"(b)); return r;
}
__device__ __forceinline__ void upk2(u64 v, float& a, float& b) {
    asm("mov.b64 {%0,%1},%2;" : "=f"(a), "=f"(b) : "l"(v));
}
__device__ __forceinline__ u64 ffma2(u64 a, u64 b, u64 c) {
    u64 d; asm("fma.rn.f32x2 %0,%1,%2,%3;" : "=l"(d) : "l"(a), "l"(b), "l"(c)); return d;
}
__device__ __forceinline__ u64 fadd2(u64 a, u64 b) {
    u64 d; asm("add.rn.f32x2 %0,%1,%2;" : "=l"(d) : "l"(a), "l"(b)); return d;
}
__device__ __forceinline__ float sigm(float x) { return 1.0f / (1.0f + __expf(-x)); }

using namespace nvcuda;

// ------------- scratch (static device globals) -------------
__device__ float g_aln[NSEQ * CS];
__device__ float g_sln[NSEQ * CS];
__device__ float g_a  [NSEQ * CS];
__device__ float g_t  [2 * NSEQ * CS];
__device__ float g_q  [NH * NSEQ * DH];
__device__ float g_k  [NH * NSEQ * DH];
__device__ float g_v  [NH * NSEQ * DH];
__device__ float g_g  [NH * NSEQ * DH];
__device__ float g_bias[(size_t)NH * NN];   // [h][i][j], 64 MB
__device__ float g_o  [NSEQ * HC];
__device__ float g_gate[NSEQ * CS];
__device__ u64   g_wpk[NH * 64];
__device__ float g_WH[NH];
__device__ float g_CH[NH];

// =====================================================================
// Kernel P: one-time prep of pair-bias weights (ffma2-packed).
// =====================================================================
__global__ void __launch_bounds__(128) k_prep(const float* __restrict__ lnw,
                                              const float* __restrict__ lnb,
                                              const float* __restrict__ wb) {
    int t = threadIdx.x;
    for (int idx = t; idx < NH * 64; idx += 128) {
        int h = idx >> 6, c2 = idx & 63;
        g_wpk[idx] = pk2(lnw[2*c2]     * wb[(2*c2)     * NH + h],
                         lnw[2*c2 + 1] * wb[(2*c2 + 1) * NH + h]);
    }
    if (t < NH) {
        float W = 0, C = 0;
        #pragma unroll 4
        for (int cc = 0; cc < CZ; cc++) {
            float wv = wb[cc * NH + t];
            W += lnw[cc] * wv; C += lnb[cc] * wv;
        }
        g_WH[t] = W; g_CH[t] = C;
    }
}

// =====================================================================
// Kernel 0: row layer norms of a_i and s_i.  grid 1024, block 384.
// =====================================================================
__global__ void __launch_bounds__(384) k_ln(const float* __restrict__ a_i,
                                            const float* __restrict__ s_i,
                                            const float* __restrict__ lnw) {
    __shared__ float red[12][4];
    __shared__ float bcv[4];
    int i = blockIdx.x, t = threadIdx.x;
    float av = a_i[i * CS + t];
    float sv = s_i[i * CS + t];
    float r0 = av, r1 = av * av, r2 = sv, r3 = sv * sv;
    #pragma unroll
    for (int o = 16; o > 0; o >>= 1) {
        r0 += __shfl_down_sync(0xffffffffu, r0, o);
        r1 += __shfl_down_sync(0xffffffffu, r1, o);
        r2 += __shfl_down_sync(0xffffffffu, r2, o);
        r3 += __shfl_down_sync(0xffffffffu, r3, o);
    }
    if ((t & 31) == 0) { int w = t >> 5; red[w][0]=r0; red[w][1]=r1; red[w][2]=r2; red[w][3]=r3; }
    __syncthreads();
    if (t == 0) {
        float s0=0, s1=0, s2=0, s3=0;
        #pragma unroll
        for (int w = 0; w < 12; w++) { s0+=red[w][0]; s1+=red[w][1]; s2+=red[w][2]; s3+=red[w][3]; }
        float ma = s0 * (1.0f/CS), ms = s2 * (1.0f/CS);
        float va = s1 * (1.0f/CS) - ma*ma;
        float vs = s3 * (1.0f/CS) - ms*ms;
        bcv[0]=ma; bcv[1]=rsqrtf(va + 1e-5f);
        bcv[2]=ms; bcv[3]=rsqrtf(vs + 1e-5f);
    }
    __syncthreads();
    g_aln[i*CS + t] = (av - bcv[0]) * bcv[1];
    g_sln[i*CS + t] = (sv - bcv[2]) * bcv[3] * lnw[t];
}

// =====================================================================
// Generic tf32 wmma GEMM (unchanged from R11).
// =====================================================================
#define ALD 392
#define WLD 72
#define GEMM_SMEM ((64 * ALD + CS * WLD) * 4)

__global__ void __launch_bounds__(256) k_gemm(const float* __restrict__ Aext,
                                              const float* __restrict__ W0,
                                              const float* __restrict__ W1,
                                              const float* __restrict__ W2,
                                              const float* __restrict__ W3,
                                              const float* __restrict__ bias,
                                              float* __restrict__ outp,
                                              int asel, int mode) {
    extern __shared__ float gsm[];
    float* Asm = gsm;
    float* Wsm = gsm + 64 * ALD;
    float* Csm = Wsm;
    int t = threadIdx.x, w = t >> 5;
    int i0 = blockIdx.y * 64;
    int c0 = blockIdx.x * 64;
    int z  = blockIdx.z;
    const float* Ap = (asel == 0) ? g_sln : (asel == 1) ? g_a : (asel == 2) ? Aext : g_o;
    const float* W  = (z == 0) ? W0 : (z == 1) ? W1 : (z == 2) ? W2 : W3;

    const float4* A4 = (const float4*)(Ap + (size_t)i0 * CS);
    #pragma unroll
    for (int p = 0; p < 24; p++) {
        int idx = t + p * 256;
        int row = idx / 96, c4 = idx % 96;
        float4 v = A4[row * 96 + c4];
        float* dst = Asm + row * ALD + c4 * 4;
        dst[0] = wmma::__float_to_tf32(v.x);
        dst[1] = wmma::__float_to_tf32(v.y);
        dst[2] = wmma::__float_to_tf32(v.z);
        dst[3] = wmma::__float_to_tf32(v.w);
    }
    #pragma unroll
    for (int p = 0; p < 24; p++) {
        int idx = t + p * 256;
        int row = idx >> 4, c4 = idx & 15;
        float4 v = *(const float4*)(W + (size_t)row * CS + c0 + c4 * 4);
        float* dst = Wsm + row * WLD + c4 * 4;
        dst[0] = wmma::__float_to_tf32(v.x);
        dst[1] = wmma::__float_to_tf32(v.y);
        dst[2] = wmma::__float_to_tf32(v.z);
        dst[3] = wmma::__float_to_tf32(v.w);
    }
    __syncthreads();

    wmma::fragment<wmma::matrix_a, 16, 16, 8, wmma::precision::tf32, wmma::row_major> fa;
    wmma::fragment<wmma::matrix_b, 16, 16, 8, wmma::precision::tf32, wmma::row_major> fb0, fb1;
    wmma::fragment<wmma::accumulator, 16, 16, 8, float> fc0, fc1;
    wmma::fill_fragment(fc0, 0.0f);
    wmma::fill_fragment(fc1, 0.0f);
    int wr = w >> 1, wc = w & 1;
    const float* abase = Asm + wr * 16 * ALD;
    const float* bbase = Wsm + wc * 32;
    #pragma unroll 8
    for (int k = 0; k < 48; k++) {
        wmma::load_matrix_sync(fa, abase + k * 8, ALD);
        wmma::load_matrix_sync(fb0, bbase + k * 8 * WLD, WLD);
        wmma::load_matrix_sync(fb1, bbase + k * 8 * WLD + 16, WLD);
        wmma::mma_sync(fc0, fa, fb0, fc0);
        wmma::mma_sync(fc1, fa, fb1, fc1);
    }
    __syncthreads();
    wmma::store_matrix_sync(Csm + wr * 16 * WLD + wc * 32, fc0, WLD, wmma::mem_row_major);
    wmma::store_matrix_sync(Csm + wr * 16 * WLD + wc * 32 + 16, fc1, WLD, wmma::mem_row_major);
    __syncthreads();

    #pragma unroll
    for (int p = 0; p < 16; p++) {
        int idx = t + p * 256;
        int r = idx >> 6, c = idx & 63;
        float v = Csm[r * WLD + c];
        int gi = i0 + r, gc = c0 + c;
        if (mode == 0) {
            g_t[(size_t)z * (NSEQ * CS) + gi * CS + gc] = v;
        } else if (mode == 1) {
            int h = gc / DH, d = gc - h * DH;
            int oidx = h * (NSEQ * DH) + gi * DH + d;
            if (z == 0)      g_q[oidx] = (v + bias[gc]) * RSQRT_D;
            else if (z == 1) g_k[oidx] = v;
            else if (z == 2) g_v[oidx] = v;
            else             g_g[oidx] = sigm(v);
        } else if (mode == 2) {
            g_gate[gi * CS + gc] = sigm(v + bias[gc]);
        } else {
            outp[gi * CS + gc] = g_gate[gi * CS + gc] * v;
        }
    }
}

// =====================================================================
// AdaLN elementwise epilogue.
// =====================================================================
__global__ void __launch_bounds__(384) k_adaln_ep(const float* __restrict__ bs) {
    int i = blockIdx.x, c = threadIdx.x;
    int idx = i * CS + c;
    g_a[idx] = sigm(g_t[idx] + bs[c]) * g_aln[idx] + g_t[NSEQ * CS + idx];
}

// =====================================================================
// Kernel 3: pair bias (R11 ffma2 version + i-offset). grid (8,512),
// block 128, dyn smem ~74 KB.
// =====================================================================
#define PAIR_SMEM (128*132*4 + NH*64*8 + 2*NH*4)
__global__ void __launch_bounds__(128) k_pair(const float* __restrict__ z, int ioff) {
    extern __shared__ float sm[];
    float* zs  = sm;
    u64*   wsm = (u64*)(sm + 128 * 132);
    float* WH  = (float*)(wsm + NH * 64);
    float* CH  = WH + NH;
    int t  = threadIdx.x;
    int i  = ioff + blockIdx.y;
    int j0 = blockIdx.x * 128;

    #pragma unroll
    for (int p = 0; p < 8; p++) wsm[t + p * 128] = g_wpk[t + p * 128];
    if (t < NH)            WH[t]      = g_WH[t];
    else if (t < 2 * NH)   CH[t - NH] = g_CH[t - NH];

    const float4* zg = (const float4*)(z + (size_t)i * (NSEQ * CZ) + (size_t)j0 * CZ);
    #pragma unroll
    for (int p = 0; p < 32; p++) {
        int f = t + p * 128;
        int jl = f >> 5, c4 = f & 31;
        *(float4*)&zs[jl * 132 + c4 * 4] = zg[(size_t)jl * 32 + c4];
    }
    __syncthreads();

    u64 acc[NH];
    #pragma unroll
    for (int h = 0; h < NH; h++) acc[h] = 0ull;
    u64 s2 = 0ull, q2 = 0ull;
    const float* zr = zs + t * 132;
    #pragma unroll 8
    for (int c4 = 0; c4 < 32; c4++) {
        float4 v = *(const float4*)&zr[c4 * 4];
        u64 v01 = pk2(v.x, v.y), v23 = pk2(v.z, v.w);
        s2 = fadd2(s2, fadd2(v01, v23));
        q2 = ffma2(v01, v01, q2);
        q2 = ffma2(v23, v23, q2);
        const u64* base = wsm + 2 * c4;
        #pragma unroll
        for (int h = 0; h < NH; h++) {
            ulonglong2 wv2 = *(const ulonglong2*)(base + h * 64);
            acc[h] = ffma2(v01, wv2.x, acc[h]);
            acc[h] = ffma2(v23, wv2.y, acc[h]);
        }
    }
    float sa, sb, qa, qb;
    upk2(s2, sa, sb); upk2(q2, qa, qb);
    float mean = (sa + sb) * (1.0f / CZ);
    float var  = (qa + qb) * (1.0f / CZ) - mean * mean;
    float rstd = rsqrtf(var + 1e-5f);
    int j = j0 + t;
    float* bo = g_bias + (size_t)i * NSEQ + j;
    #pragma unroll
    for (int h = 0; h < NH; h++) {
        float x0, x1; upk2(acc[h], x0, x1);
        bo[(size_t)h * NN] = ((x0 + x1) - mean * WH[h]) * rstd + CH[h];
    }
}

// =====================================================================
// Kernel 4: two-pass flash attention, 2 query-rows per warp (+ i-offset).
// grid (32,16), block 256, dyn smem 208 KB.
// =====================================================================
#define ATT_SMEM (2 * NSEQ * 13 * 8)
__global__ void __launch_bounds__(256) k_attn(int ioff) {
    extern __shared__ __align__(16) u64 sm8[];
    u64* ks_ = sm8;
    u64* vs_ = sm8 + NSEQ * 13;
    int h  = blockIdx.y;
    int i0 = ioff + blockIdx.x * 16;
    int t  = threadIdx.x;
    const float4* kg4 = (const float4*)(g_k + (size_t)h * NSEQ * DH);
    const float4* vg4 = (const float4*)(g_v + (size_t)h * NSEQ * DH);
    for (int idx = t; idx < NSEQ * 6; idx += 256) {
        int j = idx / 6, q4 = idx - j * 6;
        float4 kv = kg4[idx];
        ks_[j * 13 + 2 * q4]     = pk2(kv.x, kv.y);
        ks_[j * 13 + 2 * q4 + 1] = pk2(kv.z, kv.w);
        float4 vv = vg4[idx];
        vs_[j * 13 + 2 * q4]     = pk2(vv.x, vv.y);
        vs_[j * 13 + 2 * q4 + 1] = pk2(vv.z, vv.w);
    }
    __syncthreads();
    int w = t >> 5, lane = t & 31;
    int iA = i0 + 2 * w, iB = iA + 1;

    u64 qpA[12], qpB[12];
    {
        const float4* qgA = (const float4*)(g_q + ((size_t)h * NSEQ + iA) * DH);
        const float4* qgB = (const float4*)(g_q + ((size_t)h * NSEQ + iB) * DH);
        #pragma unroll
        for (int p = 0; p < 6; p++) {
            float4 qa = qgA[p];
            qpA[2 * p]     = pk2(qa.x, qa.y);
            qpA[2 * p + 1] = pk2(qa.z, qa.w);
            float4 qb = qgB[p];
            qpB[2 * p]     = pk2(qb.x, qb.y);
            qpB[2 * p + 1] = pk2(qb.z, qb.w);
        }
    }
    const float* bpA = g_bias + (size_t)h * NN + (size_t)iA * NSEQ;
    const float* bpB = bpA + NSEQ;

    float lgsA[32], lgsB[32];
    float mxA = -1e30f, mxB = -1e30f;
    #pragma unroll
    for (int s = 0; s < 32; s++) {
        int j = s * 32 + lane;
        const u64* kr = ks_ + j * 13;
        u64 a0 = 0ull, a1 = 0ull, b0 = 0ull, b1 = 0ull;
        #pragma unroll
        for (int p = 0; p < 12; p += 2) {
            u64 k0 = kr[p], k1 = kr[p + 1];
            a0 = ffma2(qpA[p],     k0, a0);
            a1 = ffma2(qpA[p + 1], k1, a1);
            b0 = ffma2(qpB[p],     k0, b0);
            b1 = ffma2(qpB[p + 1], k1, b1);
        }
        float x0, x1, y0, y1;
        upk2(a0, x0, x1); upk2(a1, y0, y1);
        float lgA = bpA[j] + ((x0 + x1) + (y0 + y1));
        upk2(b0, x0, x1); upk2(b1, y0, y1);
        float lgB = bpB[j] + ((x0 + x1) + (y0 + y1));
        lgsA[s] = lgA; mxA = fmaxf(mxA, lgA);
        lgsB[s] = lgB; mxB = fmaxf(mxB, lgB);
    }
    #pragma unroll
    for (int off = 16; off > 0; off >>= 1) {
        mxA = fmaxf(mxA, __shfl_xor_sync(0xffffffffu, mxA, off));
        mxB = fmaxf(mxB, __shfl_xor_sync(0xffffffffu, mxB, off));
    }

    float lA = 0.0f, lB = 0.0f;
    u64 oA[12], oB[12];
    #pragma unroll
    for (int p = 0; p < 12; p++) { oA[p] = 0ull; oB[p] = 0ull; }
    #pragma unroll
    for (int s = 0; s < 32; s++) {
        float pA = __expf(lgsA[s] - mxA);
        float pB = __expf(lgsB[s] - mxB);
        lA += pA; lB += pB;
        u64 ppA = pk2(pA, pA), ppB = pk2(pB, pB);
        const u64* vr = vs_ + (s * 32 + lane) * 13;
        #pragma unroll
        for (int q = 0; q < 12; q++) {
            u64 vv = vr[q];
            oA[q] = ffma2(ppA, vv, oA[q]);
            oB[q] = ffma2(ppB, vv, oB[q]);
        }
    }
    #pragma unroll
    for (int off = 16; off > 0; off >>= 1) {
        lA += __shfl_xor_sync(0xffffffffu, lA, off);
        lB += __shfl_xor_sync(0xffffffffu, lB, off);
    }
    float fA[DH], fB[DH];
    #pragma unroll
    for (int q = 0; q < 12; q++) {
        upk2(oA[q], fA[2 * q], fA[2 * q + 1]);
        upk2(oB[q], fB[2 * q], fB[2 * q + 1]);
    }
    #pragma unroll
    for (int d = 0; d < DH; d++) {
        #pragma unroll
        for (int off = 16; off > 0; off >>= 1) {
            fA[d] += __shfl_xor_sync(0xffffffffu, fA[d], off);
            fB[d] += __shfl_xor_sync(0xffffffffu, fB[d], off);
        }
    }
    if (lane == 0) {
        float invA = 1.0f / lA;
        const float* ggA = g_g + ((size_t)h * NSEQ + iA) * DH;
        float* opA = g_o + (size_t)iA * HC + h * DH;
        #pragma unroll
        for (int d = 0; d < DH; d++) opA[d] = fA[d] * invA * ggA[d];
        float invB = 1.0f / lB;
        const float* ggB = g_g + ((size_t)h * NSEQ + iB) * DH;
        float* opB = g_o + (size_t)iB * HC + h * DH;
        #pragma unroll
        for (int d = 0; d < DH; d++) opB[d] = fB[d] * invB * ggB[d];
    }
}

// =====================================================================
extern "C" void kernel_launch(void* const* d_in, const int* in_sizes, int n_in,
                              void* d_out, int out_size) {
    const float* a_i   = (const float*)d_in[0];
    const float* s_i   = (const float*)d_in[1];
    const float* z     = (const float*)d_in[2];
    const float* lns_w = (const float*)d_in[3];
    const float* aws   = (const float*)d_in[4];
    const float* abs_  = (const float*)d_in[5];
    const float* awns  = (const float*)d_in[6];
    const float* wq    = (const float*)d_in[7];
    const float* bq    = (const float*)d_in[8];
    const float* wk    = (const float*)d_in[9];
    const float* wv    = (const float*)d_in[10];
    const float* lnb_w = (const float*)d_in[11];
    const float* lnb_b = (const float*)d_in[12];
    const float* wb    = (const float*)d_in[13];
    const float* wg    = (const float*)d_in[14];
    const float* wo    = (const float*)d_in[15];
    const float* ws2   = (const float*)d_in[16];
    const float* bs2   = (const float*)d_in[17];
    float* out = (float*)d_out;

    static cudaStream_t sA = 0, sB = 0;
    static cudaEvent_t evF = 0, evP1 = 0, evP2 = 0, evB = 0;
    static int inited = 0;
    if (!inited) {
        cudaStreamCreateWithFlags(&sA, cudaStreamNonBlocking);
        cudaStreamCreateWithFlags(&sB, cudaStreamNonBlocking);
        cudaEventCreateWithFlags(&evF,  cudaEventDisableTiming);
        cudaEventCreateWithFlags(&evP1, cudaEventDisableTiming);
        cudaEventCreateWithFlags(&evP2, cudaEventDisableTiming);
        cudaEventCreateWithFlags(&evB,  cudaEventDisableTiming);
        cudaFuncSetAttribute(k_pair, cudaFuncAttributeMaxDynamicSharedMemorySize, PAIR_SMEM);
        cudaFuncSetAttribute(k_attn, cudaFuncAttributeMaxDynamicSharedMemorySize, ATT_SMEM);
        cudaFuncSetAttribute(k_gemm, cudaFuncAttributeMaxDynamicSharedMemorySize, GEMM_SMEM);
        inited = 1;
    }

    // fork
    cudaEventRecord(evF, 0);
    cudaStreamWaitEvent(sA, evF, 0);
    cudaStreamWaitEvent(sB, evF, 0);

    // launch #1: pair-weight prep (stream A)
    k_prep<<<1, 128, 0, sA>>>(lnb_w, lnb_b, wb);

    // launches #2-#5: LN -> AdaLN -> QKV/gate chain (default stream)
    k_ln<<<NSEQ, CS>>>(a_i, s_i, lns_w);
    k_gemm<<<dim3(6, 16, 2), 256, GEMM_SMEM>>>(nullptr, aws, awns, nullptr, nullptr,
                                               nullptr, nullptr, 0, 0);
    k_adaln_ep<<<NSEQ, CS>>>(abs_);
    k_gemm<<<dim3(6, 16, 4), 256, GEMM_SMEM>>>(nullptr, wq, wk, wv, wg,
                                               bq, nullptr, 1, 1);

    // launch #6 (ncu-profiled): pair bias, first i-half (stream A)
    k_pair<<<dim3(8, 512), 128, PAIR_SMEM, sA>>>(z, 0);
    cudaEventRecord(evP1, sA);
    // launch #7: pair bias, second i-half
    k_pair<<<dim3(8, 512), 128, PAIR_SMEM, sA>>>(z, 512);
    cudaEventRecord(evP2, sA);

    // launch #8: final conditioning gate (stream B, independent)
    k_gemm<<<dim3(6, 16, 1), 256, GEMM_SMEM, sB>>>(s_i, ws2, nullptr, nullptr, nullptr,
                                                   bs2, nullptr, 2, 2);
    cudaEventRecord(evB, sB);

    // attention first half overlaps pair second half
    cudaStreamWaitEvent(0, evP1, 0);
    k_attn<<<dim3(32, 16), 256, ATT_SMEM>>>(0);
    cudaStreamWaitEvent(0, evP2, 0);
    k_attn<<<dim3(32, 16), 256, ATT_SMEM>>>(512);

    // output projection
    cudaStreamWaitEvent(0, evB, 0);
    k_gemm<<<dim3(6, 16, 1), 256, GEMM_SMEM>>>(nullptr, wo, nullptr, nullptr, nullptr,
                                               nullptr, out, 3, 3);
}

// round 16
// speedup vs baseline: 1.1027x; 1.1027x over previous
#include <cuda_runtime.h>
#include <cuda_bf16.h>
#include <mma.h>
#include <math.h>

#define NSEQ 1024
#define CS   384
#define CZ   128
#define NH   16
#define DH   24
#define HC   384
#define NN   (NSEQ*NSEQ)
#define RSQRT_D 0.2041241452319315f

typedef unsigned long long u64;
typedef unsigned int u32;

__device__ __forceinline__ u64 pk2(float a, float b) {
    u64 r; asm("mov.b64 %0,{%1,%2};" : "=l"(r) : "f"(a), "f"(b)); return r;
}
__device__ __forceinline__ void upk2(u64 v, float& a, float& b) {
    asm("mov.b64 {%0,%1},%2;" : "=f"(a), "=f"(b) : "l"(v));
}
__device__ __forceinline__ u64 ffma2(u64 a, u64 b, u64 c) {
    u64 d; asm("fma.rn.f32x2 %0,%1,%2,%3;" : "=l"(d) : "l"(a), "l"(b), "l"(c)); return d;
}
__device__ __forceinline__ u64 fadd2(u64 a, u64 b) {
    u64 d; asm("add.rn.f32x2 %0,%1,%2;" : "=l"(d) : "l"(a), "l"(b)); return d;
}
__device__ __forceinline__ float sigm(float x) { return 1.0f / (1.0f + __expf(-x)); }

using namespace nvcuda;

// ------------- scratch (static device globals) -------------
__device__ float g_aln[NSEQ * CS];
__device__ float g_sln[NSEQ * CS];
__device__ float g_a  [NSEQ * CS];
__device__ float g_t  [2 * NSEQ * CS];
__device__ float g_q  [NH * NSEQ * DH];
__device__ float g_k  [NH * NSEQ * DH];
__device__ float g_v  [NH * NSEQ * DH];
__device__ float g_g  [NH * NSEQ * DH];
__device__ float g_bias[(size_t)NH * NN];   // [h][i][j], 64 MB
__device__ float g_o  [NSEQ * HC];
__device__ float g_gate[NSEQ * CS];
__device__ u64   g_wpk[NH * 64];
__device__ float g_WH[NH];
__device__ float g_CH[NH];

// =====================================================================
// Kernel P: one-time prep of pair-bias weights (ffma2-packed).
// =====================================================================
__global__ void __launch_bounds__(128) k_prep(const float* __restrict__ lnw,
                                              const float* __restrict__ lnb,
                                              const float* __restrict__ wb) {
    int t = threadIdx.x;
    for (int idx = t; idx < NH * 64; idx += 128) {
        int h = idx >> 6, c2 = idx & 63;
        g_wpk[idx] = pk2(lnw[2*c2]     * wb[(2*c2)     * NH + h],
                         lnw[2*c2 + 1] * wb[(2*c2 + 1) * NH + h]);
    }
    if (t < NH) {
        float W = 0, C = 0;
        #pragma unroll 4
        for (int cc = 0; cc < CZ; cc++) {
            float wv = wb[cc * NH + t];
            W += lnw[cc] * wv; C += lnb[cc] * wv;
        }
        g_WH[t] = W; g_CH[t] = C;
    }
}

// =====================================================================
// Kernel 0: row layer norms of a_i and s_i.  grid 1024, block 384.
// =====================================================================
__global__ void __launch_bounds__(384) k_ln(const float* __restrict__ a_i,
                                            const float* __restrict__ s_i,
                                            const float* __restrict__ lnw) {
    __shared__ float red[12][4];
    __shared__ float bcv[4];
    int i = blockIdx.x, t = threadIdx.x;
    float av = a_i[i * CS + t];
    float sv = s_i[i * CS + t];
    float r0 = av, r1 = av * av, r2 = sv, r3 = sv * sv;
    #pragma unroll
    for (int o = 16; o > 0; o >>= 1) {
        r0 += __shfl_down_sync(0xffffffffu, r0, o);
        r1 += __shfl_down_sync(0xffffffffu, r1, o);
        r2 += __shfl_down_sync(0xffffffffu, r2, o);
        r3 += __shfl_down_sync(0xffffffffu, r3, o);
    }
    if ((t & 31) == 0) { int w = t >> 5; red[w][0]=r0; red[w][1]=r1; red[w][2]=r2; red[w][3]=r3; }
    __syncthreads();
    if (t == 0) {
        float s0=0, s1=0, s2=0, s3=0;
        #pragma unroll
        for (int w = 0; w < 12; w++) { s0+=red[w][0]; s1+=red[w][1]; s2+=red[w][2]; s3+=red[w][3]; }
        float ma = s0 * (1.0f/CS), ms = s2 * (1.0f/CS);
        float va = s1 * (1.0f/CS) - ma*ma;
        float vs = s3 * (1.0f/CS) - ms*ms;
        bcv[0]=ma; bcv[1]=rsqrtf(va + 1e-5f);
        bcv[2]=ms; bcv[3]=rsqrtf(vs + 1e-5f);
    }
    __syncthreads();
    g_aln[i*CS + t] = (av - bcv[0]) * bcv[1];
    g_sln[i*CS + t] = (sv - bcv[2]) * bcv[3] * lnw[t];
}

// =====================================================================
// Generic tf32 wmma GEMM, K-CHUNKED (3 chunks of 128) so smem = 71 KB
// and blocks co-reside with k_pair (74 KB): 74 + 2*71 = 216 <= 227 KB.
// Tile 64x64, block 256 (8 warps: 4r x 2c), grid (6,16,nz).
// Epilogue by mode: 0 raw->g_t[z]; 1 qkvg scatter; 2 gate; 3 out.
// A source by asel: 0=g_sln, 1=g_a, 2=param A, 3=g_o.
// =====================================================================
#define ALD 136
#define WLD 72
#define KCH 128
#define GEMM_SMEM ((64 * ALD + KCH * WLD) * 4)

__global__ void __launch_bounds__(256) k_gemm(const float* __restrict__ Aext,
                                              const float* __restrict__ W0,
                                              const float* __restrict__ W1,
                                              const float* __restrict__ W2,
                                              const float* __restrict__ W3,
                                              const float* __restrict__ bias,
                                              float* __restrict__ outp,
                                              int asel, int mode) {
    extern __shared__ float gsm[];
    float* Asm = gsm;                  // [64][136]
    float* Wsm = gsm + 64 * ALD;       // [128][72]
    float* Csm = Wsm;                  // reused after mma loop (needs 64x72)
    int t = threadIdx.x, w = t >> 5;
    int i0 = blockIdx.y * 64;
    int c0 = blockIdx.x * 64;
    int z  = blockIdx.z;
    const float* Ap = (asel == 0) ? g_sln : (asel == 1) ? g_a : (asel == 2) ? Aext : g_o;
    const float* W  = (z == 0) ? W0 : (z == 1) ? W1 : (z == 2) ? W2 : W3;

    wmma::fragment<wmma::matrix_a, 16, 16, 8, wmma::precision::tf32, wmma::row_major> fa;
    wmma::fragment<wmma::matrix_b, 16, 16, 8, wmma::precision::tf32, wmma::row_major> fb0, fb1;
    wmma::fragment<wmma::accumulator, 16, 16, 8, float> fc0, fc1;
    wmma::fill_fragment(fc0, 0.0f);
    wmma::fill_fragment(fc1, 0.0f);
    int wr = w >> 1, wc = w & 1;

    for (int ch = 0; ch < CS / KCH; ch++) {
        int k0 = ch * KCH;
        __syncthreads();                      // previous chunk fully consumed
        // stage A band [64 x 128] as tf32: 2048 float4, 8/thread
        #pragma unroll
        for (int p = 0; p < 8; p++) {
            int idx = t + p * 256;
            int row = idx >> 5, c4 = idx & 31;
            float4 v = *(const float4*)(Ap + (size_t)(i0 + row) * CS + k0 + c4 * 4);
            float* dst = Asm + row * ALD + c4 * 4;
            dst[0] = wmma::__float_to_tf32(v.x);
            dst[1] = wmma::__float_to_tf32(v.y);
            dst[2] = wmma::__float_to_tf32(v.z);
            dst[3] = wmma::__float_to_tf32(v.w);
        }
        // stage W band [128 x 64] as tf32: 2048 float4, 8/thread
        #pragma unroll
        for (int p = 0; p < 8; p++) {
            int idx = t + p * 256;
            int row = idx >> 4, c4 = idx & 15;
            float4 v = *(const float4*)(W + (size_t)(k0 + row) * CS + c0 + c4 * 4);
            float* dst = Wsm + row * WLD + c4 * 4;
            dst[0] = wmma::__float_to_tf32(v.x);
            dst[1] = wmma::__float_to_tf32(v.y);
            dst[2] = wmma::__float_to_tf32(v.z);
            dst[3] = wmma::__float_to_tf32(v.w);
        }
        __syncthreads();
        const float* abase = Asm + wr * 16 * ALD;
        const float* bbase = Wsm + wc * 32;
        #pragma unroll 8
        for (int k = 0; k < KCH / 8; k++) {
            wmma::load_matrix_sync(fa, abase + k * 8, ALD);
            wmma::load_matrix_sync(fb0, bbase + k * 8 * WLD, WLD);
            wmma::load_matrix_sync(fb1, bbase + k * 8 * WLD + 16, WLD);
            wmma::mma_sync(fc0, fa, fb0, fc0);
            wmma::mma_sync(fc1, fa, fb1, fc1);
        }
    }
    __syncthreads();
    wmma::store_matrix_sync(Csm + wr * 16 * WLD + wc * 32, fc0, WLD, wmma::mem_row_major);
    wmma::store_matrix_sync(Csm + wr * 16 * WLD + wc * 32 + 16, fc1, WLD, wmma::mem_row_major);
    __syncthreads();

    #pragma unroll
    for (int p = 0; p < 16; p++) {
        int idx = t + p * 256;
        int r = idx >> 6, c = idx & 63;
        float v = Csm[r * WLD + c];
        int gi = i0 + r, gc = c0 + c;
        if (mode == 0) {
            g_t[(size_t)z * (NSEQ * CS) + gi * CS + gc] = v;
        } else if (mode == 1) {
            int h = gc / DH, d = gc - h * DH;
            int oidx = h * (NSEQ * DH) + gi * DH + d;
            if (z == 0)      g_q[oidx] = (v + bias[gc]) * RSQRT_D;
            else if (z == 1) g_k[oidx] = v;
            else if (z == 2) g_v[oidx] = v;
            else             g_g[oidx] = sigm(v);
        } else if (mode == 2) {
            g_gate[gi * CS + gc] = sigm(v + bias[gc]);
        } else {
            outp[gi * CS + gc] = g_gate[gi * CS + gc] * v;
        }
    }
}

// =====================================================================
// AdaLN elementwise epilogue.
// =====================================================================
__global__ void __launch_bounds__(384) k_adaln_ep(const float* __restrict__ bs) {
    int i = blockIdx.x, c = threadIdx.x;
    int idx = i * CS + c;
    g_a[idx] = sigm(g_t[idx] + bs[c]) * g_aln[idx] + g_t[NSEQ * CS + idx];
}

// =====================================================================
// Kernel 3: pair bias (R11 ffma2 version). grid (8,1024), block 128,
// dyn smem ~74 KB (3 blocks/SM; leaves room for 2 gemm blocks).
// =====================================================================
#define PAIR_SMEM (128*132*4 + NH*64*8 + 2*NH*4)
__global__ void __launch_bounds__(128) k_pair(const float* __restrict__ z) {
    extern __shared__ float sm[];
    float* zs  = sm;
    u64*   wsm = (u64*)(sm + 128 * 132);
    float* WH  = (float*)(wsm + NH * 64);
    float* CH  = WH + NH;
    int t  = threadIdx.x;
    int i  = blockIdx.y;
    int j0 = blockIdx.x * 128;

    #pragma unroll
    for (int p = 0; p < 8; p++) wsm[t + p * 128] = g_wpk[t + p * 128];
    if (t < NH)            WH[t]      = g_WH[t];
    else if (t < 2 * NH)   CH[t - NH] = g_CH[t - NH];

    const float4* zg = (const float4*)(z + (size_t)i * (NSEQ * CZ) + (size_t)j0 * CZ);
    #pragma unroll
    for (int p = 0; p < 32; p++) {
        int f = t + p * 128;
        int jl = f >> 5, c4 = f & 31;
        *(float4*)&zs[jl * 132 + c4 * 4] = zg[(size_t)jl * 32 + c4];
    }
    __syncthreads();

    u64 acc[NH];
    #pragma unroll
    for (int h = 0; h < NH; h++) acc[h] = 0ull;
    u64 s2 = 0ull, q2 = 0ull;
    const float* zr = zs + t * 132;
    #pragma unroll 8
    for (int c4 = 0; c4 < 32; c4++) {
        float4 v = *(const float4*)&zr[c4 * 4];
        u64 v01 = pk2(v.x, v.y), v23 = pk2(v.z, v.w);
        s2 = fadd2(s2, fadd2(v01, v23));
        q2 = ffma2(v01, v01, q2);
        q2 = ffma2(v23, v23, q2);
        const u64* base = wsm + 2 * c4;
        #pragma unroll
        for (int h = 0; h < NH; h++) {
            ulonglong2 wv2 = *(const ulonglong2*)(base + h * 64);
            acc[h] = ffma2(v01, wv2.x, acc[h]);
            acc[h] = ffma2(v23, wv2.y, acc[h]);
        }
    }
    float sa, sb, qa, qb;
    upk2(s2, sa, sb); upk2(q2, qa, qb);
    float mean = (sa + sb) * (1.0f / CZ);
    float var  = (qa + qb) * (1.0f / CZ) - mean * mean;
    float rstd = rsqrtf(var + 1e-5f);
    int j = j0 + t;
    float* bo = g_bias + (size_t)i * NSEQ + j;
    #pragma unroll
    for (int h = 0; h < NH; h++) {
        float x0, x1; upk2(acc[h], x0, x1);
        bo[(size_t)h * NN] = ((x0 + x1) - mean * WH[h]) * rstd + CH[h];
    }
}

// =====================================================================
// Kernel 4: two-pass flash attention, 2 query-rows per warp (R11).
// grid (64,16), block 256, dyn smem 208 KB.
// =====================================================================
#define ATT_SMEM (2 * NSEQ * 13 * 8)
__global__ void __launch_bounds__(256) k_attn() {
    extern __shared__ __align__(16) u64 sm8[];
    u64* ks_ = sm8;
    u64* vs_ = sm8 + NSEQ * 13;
    int h  = blockIdx.y;
    int i0 = blockIdx.x * 16;
    int t  = threadIdx.x;
    const float4* kg4 = (const float4*)(g_k + (size_t)h * NSEQ * DH);
    const float4* vg4 = (const float4*)(g_v + (size_t)h * NSEQ * DH);
    for (int idx = t; idx < NSEQ * 6; idx += 256) {
        int j = idx / 6, q4 = idx - j * 6;
        float4 kv = kg4[idx];
        ks_[j * 13 + 2 * q4]     = pk2(kv.x, kv.y);
        ks_[j * 13 + 2 * q4 + 1] = pk2(kv.z, kv.w);
        float4 vv = vg4[idx];
        vs_[j * 13 + 2 * q4]     = pk2(vv.x, vv.y);
        vs_[j * 13 + 2 * q4 + 1] = pk2(vv.z, vv.w);
    }
    __syncthreads();
    int w = t >> 5, lane = t & 31;
    int iA = i0 + 2 * w, iB = iA + 1;

    u64 qpA[12], qpB[12];
    {
        const float4* qgA = (const float4*)(g_q + ((size_t)h * NSEQ + iA) * DH);
        const float4* qgB = (const float4*)(g_q + ((size_t)h * NSEQ + iB) * DH);
        #pragma unroll
        for (int p = 0; p < 6; p++) {
            float4 qa = qgA[p];
            qpA[2 * p]     = pk2(qa.x, qa.y);
            qpA[2 * p + 1] = pk2(qa.z, qa.w);
            float4 qb = qgB[p];
            qpB[2 * p]     = pk2(qb.x, qb.y);
            qpB[2 * p + 1] = pk2(qb.z, qb.w);
        }
    }
    const float* bpA = g_bias + (size_t)h * NN + (size_t)iA * NSEQ;
    const float* bpB = bpA + NSEQ;

    float lgsA[32], lgsB[32];
    float mxA = -1e30f, mxB = -1e30f;
    #pragma unroll
    for (int s = 0; s < 32; s++) {
        int j = s * 32 + lane;
        const u64* kr = ks_ + j * 13;
        u64 a0 = 0ull, a1 = 0ull, b0 = 0ull, b1 = 0ull;
        #pragma unroll
        for (int p = 0; p < 12; p += 2) {
            u64 k0 = kr[p], k1 = kr[p + 1];
            a0 = ffma2(qpA[p],     k0, a0);
            a1 = ffma2(qpA[p + 1], k1, a1);
            b0 = ffma2(qpB[p],     k0, b0);
            b1 = ffma2(qpB[p + 1], k1, b1);
        }
        float x0, x1, y0, y1;
        upk2(a0, x0, x1); upk2(a1, y0, y1);
        float lgA = bpA[j] + ((x0 + x1) + (y0 + y1));
        upk2(b0, x0, x1); upk2(b1, y0, y1);
        float lgB = bpB[j] + ((x0 + x1) + (y0 + y1));
        lgsA[s] = lgA; mxA = fmaxf(mxA, lgA);
        lgsB[s] = lgB; mxB = fmaxf(mxB, lgB);
    }
    #pragma unroll
    for (int off = 16; off > 0; off >>= 1) {
        mxA = fmaxf(mxA, __shfl_xor_sync(0xffffffffu, mxA, off));
        mxB = fmaxf(mxB, __shfl_xor_sync(0xffffffffu, mxB, off));
    }

    float lA = 0.0f, lB = 0.0f;
    u64 oA[12], oB[12];
    #pragma unroll
    for (int p = 0; p < 12; p++) { oA[p] = 0ull; oB[p] = 0ull; }
    #pragma unroll
    for (int s = 0; s < 32; s++) {
        float pA = __expf(lgsA[s] - mxA);
        float pB = __expf(lgsB[s] - mxB);
        lA += pA; lB += pB;
        u64 ppA = pk2(pA, pA), ppB = pk2(pB, pB);
        const u64* vr = vs_ + (s * 32 + lane) * 13;
        #pragma unroll
        for (int q = 0; q < 12; q++) {
            u64 vv = vr[q];
            oA[q] = ffma2(ppA, vv, oA[q]);
            oB[q] = ffma2(ppB, vv, oB[q]);
        }
    }
    #pragma unroll
    for (int off = 16; off > 0; off >>= 1) {
        lA += __shfl_xor_sync(0xffffffffu, lA, off);
        lB += __shfl_xor_sync(0xffffffffu, lB, off);
    }
    float fA[DH], fB[DH];
    #pragma unroll
    for (int q = 0; q < 12; q++) {
        upk2(oA[q], fA[2 * q], fA[2 * q + 1]);
        upk2(oB[q], fB[2 * q], fB[2 * q + 1]);
    }
    #pragma unroll
    for (int d = 0; d < DH; d++) {
        #pragma unroll
        for (int off = 16; off > 0; off >>= 1) {
            fA[d] += __shfl_xor_sync(0xffffffffu, fA[d], off);
            fB[d] += __shfl_xor_sync(0xffffffffu, fB[d], off);
        }
    }
    if (lane == 0) {
        float invA = 1.0f / lA;
        const float* ggA = g_g + ((size_t)h * NSEQ + iA) * DH;
        float* opA = g_o + (size_t)iA * HC + h * DH;
        #pragma unroll
        for (int d = 0; d < DH; d++) opA[d] = fA[d] * invA * ggA[d];
        float invB = 1.0f / lB;
        const float* ggB = g_g + ((size_t)h * NSEQ + iB) * DH;
        float* opB = g_o + (size_t)iB * HC + h * DH;
        #pragma unroll
        for (int d = 0; d < DH; d++) opB[d] = fB[d] * invB * ggB[d];
    }
}

// =====================================================================
extern "C" void kernel_launch(void* const* d_in, const int* in_sizes, int n_in,
                              void* d_out, int out_size) {
    const float* a_i   = (const float*)d_in[0];
    const float* s_i   = (const float*)d_in[1];
    const float* z     = (const float*)d_in[2];
    const float* lns_w = (const float*)d_in[3];
    const float* aws   = (const float*)d_in[4];
    const float* abs_  = (const float*)d_in[5];
    const float* awns  = (const float*)d_in[6];
    const float* wq    = (const float*)d_in[7];
    const float* bq    = (const float*)d_in[8];
    const float* wk    = (const float*)d_in[9];
    const float* wv    = (const float*)d_in[10];
    const float* lnb_w = (const float*)d_in[11];
    const float* lnb_b = (const float*)d_in[12];
    const float* wb    = (const float*)d_in[13];
    const float* wg    = (const float*)d_in[14];
    const float* wo    = (const float*)d_in[15];
    const float* ws2   = (const float*)d_in[16];
    const float* bs2   = (const float*)d_in[17];
    float* out = (float*)d_out;

    static cudaStream_t sA = 0, sB = 0;
    static cudaEvent_t evF = 0, evA = 0, evB = 0;
    static int inited = 0;
    if (!inited) {
        cudaStreamCreateWithFlags(&sA, cudaStreamNonBlocking);
        cudaStreamCreateWithFlags(&sB, cudaStreamNonBlocking);
        cudaEventCreateWithFlags(&evF, cudaEventDisableTiming);
        cudaEventCreateWithFlags(&evA, cudaEventDisableTiming);
        cudaEventCreateWithFlags(&evB, cudaEventDisableTiming);
        cudaFuncSetAttribute(k_pair, cudaFuncAttributeMaxDynamicSharedMemorySize, PAIR_SMEM);
        cudaFuncSetAttribute(k_attn, cudaFuncAttributeMaxDynamicSharedMemorySize, ATT_SMEM);
        cudaFuncSetAttribute(k_gemm, cudaFuncAttributeMaxDynamicSharedMemorySize, GEMM_SMEM);
        inited = 1;
    }

    // fork
    cudaEventRecord(evF, 0);
    cudaStreamWaitEvent(sA, evF, 0);
    cudaStreamWaitEvent(sB, evF, 0);

    // stream A: pair-bias path — launched FIRST so its 8192 blocks flow
    // continuously; 71-KB gemm blocks co-reside in the gaps (74+2*71<=227).
    k_prep<<<1, 128, 0, sA>>>(lnb_w, lnb_b, wb);
    k_pair<<<dim3(8, NSEQ), 128, PAIR_SMEM, sA>>>(z);

    // stream B: final conditioning gate (tensor-core, 71 KB)
    k_gemm<<<dim3(6, 16, 1), 256, GEMM_SMEM, sB>>>(s_i, ws2, nullptr, nullptr, nullptr,
                                                   bs2, nullptr, 2, 2);

    // default stream: LN -> AdaLN -> QKV/gate chain (all 71-KB blocks,
    // genuinely concurrent with pair now)
    k_ln<<<NSEQ, CS>>>(a_i, s_i, lns_w);
    k_gemm<<<dim3(6, 16, 2), 256, GEMM_SMEM>>>(nullptr, aws, awns, nullptr, nullptr,
                                               nullptr, nullptr, 0, 0);
    k_adaln_ep<<<NSEQ, CS>>>(abs_);
    k_gemm<<<dim3(6, 16, 4), 256, GEMM_SMEM>>>(nullptr, wq, wk, wv, wg,
                                               bq, nullptr, 1, 1);

    // join
    cudaEventRecord(evA, sA);
    cudaEventRecord(evB, sB);
    cudaStreamWaitEvent(0, evA, 0);
    cudaStreamWaitEvent(0, evB, 0);

    k_attn<<<dim3(64, 16), 256, ATT_SMEM>>>();
    k_gemm<<<dim3(6, 16, 1), 256, GEMM_SMEM>>>(nullptr, wo, nullptr, nullptr, nullptr,
                                               nullptr, out, 3, 3);
}

// round 17
// speedup vs baseline: 1.1141x; 1.0104x over previous
#include <cuda_runtime.h>
#include <cuda_bf16.h>
#include <mma.h>
#include <math.h>

#define NSEQ 1024
#define CS   384
#define CZ   128
#define NH   16
#define DH   24
#define HC   384
#define NN   (NSEQ*NSEQ)
#define RSQRT_D 0.2041241452319315f

typedef unsigned long long u64;
typedef unsigned int u32;

__device__ __forceinline__ u64 pk2(float a, float b) {
    u64 r; asm("mov.b64 %0,{%1,%2};" : "=l"(r) : "f"(a), "f"(b)); return r;
}
__device__ __forceinline__ void upk2(u64 v, float& a, float& b) {
    asm("mov.b64 {%0,%1},%2;" : "=f"(a), "=f"(b) : "l"(v));
}
__device__ __forceinline__ u64 ffma2(u64 a, u64 b, u64 c) {
    u64 d; asm("fma.rn.f32x2 %0,%1,%2,%3;" : "=l"(d) : "l"(a), "l"(b), "l"(c)); return d;
}
__device__ __forceinline__ u64 fadd2(u64 a, u64 b) {
    u64 d; asm("add.rn.f32x2 %0,%1,%2;" : "=l"(d) : "l"(a), "l"(b)); return d;
}
__device__ __forceinline__ float sigm(float x) { return 1.0f / (1.0f + __expf(-x)); }

using namespace nvcuda;

// ------------- scratch (static device globals) -------------
__device__ float g_aln[NSEQ * CS];
__device__ float g_sln[NSEQ * CS];
__device__ float g_a  [NSEQ * CS];
__device__ float g_t  [2 * NSEQ * CS];
__device__ float g_q  [NH * NSEQ * DH];
__device__ float g_k  [NH * NSEQ * DH];
__device__ float g_v  [NH * NSEQ * DH];
__device__ float g_g  [NH * NSEQ * DH];
__device__ float g_bias[(size_t)NH * NN];   // [h][i][j], 64 MB
__device__ float g_o  [NSEQ * HC];
__device__ float g_gate[NSEQ * CS];
__device__ u64   g_wpk[NH * 64];
__device__ float g_WH[NH];
__device__ float g_CH[NH];

// =====================================================================
// Kernel P: one-time prep of pair-bias weights (ffma2-packed).
// =====================================================================
__global__ void __launch_bounds__(128) k_prep(const float* __restrict__ lnw,
                                              const float* __restrict__ lnb,
                                              const float* __restrict__ wb) {
    int t = threadIdx.x;
    for (int idx = t; idx < NH * 64; idx += 128) {
        int h = idx >> 6, c2 = idx & 63;
        g_wpk[idx] = pk2(lnw[2*c2]     * wb[(2*c2)     * NH + h],
                         lnw[2*c2 + 1] * wb[(2*c2 + 1) * NH + h]);
    }
    if (t < NH) {
        float W = 0, C = 0;
        #pragma unroll 4
        for (int cc = 0; cc < CZ; cc++) {
            float wv = wb[cc * NH + t];
            W += lnw[cc] * wv; C += lnb[cc] * wv;
        }
        g_WH[t] = W; g_CH[t] = C;
    }
}

// =====================================================================
// Kernel 0: row layer norms of a_i and s_i.  grid 1024, block 384.
// =====================================================================
__global__ void __launch_bounds__(384) k_ln(const float* __restrict__ a_i,
                                            const float* __restrict__ s_i,
                                            const float* __restrict__ lnw) {
    __shared__ float red[12][4];
    __shared__ float bcv[4];
    int i = blockIdx.x, t = threadIdx.x;
    float av = a_i[i * CS + t];
    float sv = s_i[i * CS + t];
    float r0 = av, r1 = av * av, r2 = sv, r3 = sv * sv;
    #pragma unroll
    for (int o = 16; o > 0; o >>= 1) {
        r0 += __shfl_down_sync(0xffffffffu, r0, o);
        r1 += __shfl_down_sync(0xffffffffu, r1, o);
        r2 += __shfl_down_sync(0xffffffffu, r2, o);
        r3 += __shfl_down_sync(0xffffffffu, r3, o);
    }
    if ((t & 31) == 0) { int w = t >> 5; red[w][0]=r0; red[w][1]=r1; red[w][2]=r2; red[w][3]=r3; }
    __syncthreads();
    if (t == 0) {
        float s0=0, s1=0, s2=0, s3=0;
        #pragma unroll
        for (int w = 0; w < 12; w++) { s0+=red[w][0]; s1+=red[w][1]; s2+=red[w][2]; s3+=red[w][3]; }
        float ma = s0 * (1.0f/CS), ms = s2 * (1.0f/CS);
        float va = s1 * (1.0f/CS) - ma*ma;
        float vs = s3 * (1.0f/CS) - ms*ms;
        bcv[0]=ma; bcv[1]=rsqrtf(va + 1e-5f);
        bcv[2]=ms; bcv[3]=rsqrtf(vs + 1e-5f);
    }
    __syncthreads();
    g_aln[i*CS + t] = (av - bcv[0]) * bcv[1];
    g_sln[i*CS + t] = (sv - bcv[2]) * bcv[3] * lnw[t];
}

// =====================================================================
// Generic tf32 wmma GEMM, K-chunked (71 KB smem; co-resides with pair).
// =====================================================================
#define ALD 136
#define WLD 72
#define KCH 128
#define GEMM_SMEM ((64 * ALD + KCH * WLD) * 4)

__global__ void __launch_bounds__(256) k_gemm(const float* __restrict__ Aext,
                                              const float* __restrict__ W0,
                                              const float* __restrict__ W1,
                                              const float* __restrict__ W2,
                                              const float* __restrict__ W3,
                                              const float* __restrict__ bias,
                                              float* __restrict__ outp,
                                              int asel, int mode) {
    extern __shared__ float gsm[];
    float* Asm = gsm;                  // [64][136]
    float* Wsm = gsm + 64 * ALD;       // [128][72]
    float* Csm = Wsm;                  // reused after mma loop
    int t = threadIdx.x, w = t >> 5;
    int i0 = blockIdx.y * 64;
    int c0 = blockIdx.x * 64;
    int z  = blockIdx.z;
    const float* Ap = (asel == 0) ? g_sln : (asel == 1) ? g_a : (asel == 2) ? Aext : g_o;
    const float* W  = (z == 0) ? W0 : (z == 1) ? W1 : (z == 2) ? W2 : W3;

    wmma::fragment<wmma::matrix_a, 16, 16, 8, wmma::precision::tf32, wmma::row_major> fa;
    wmma::fragment<wmma::matrix_b, 16, 16, 8, wmma::precision::tf32, wmma::row_major> fb0, fb1;
    wmma::fragment<wmma::accumulator, 16, 16, 8, float> fc0, fc1;
    wmma::fill_fragment(fc0, 0.0f);
    wmma::fill_fragment(fc1, 0.0f);
    int wr = w >> 1, wc = w & 1;

    for (int ch = 0; ch < CS / KCH; ch++) {
        int k0 = ch * KCH;
        __syncthreads();
        #pragma unroll
        for (int p = 0; p < 8; p++) {
            int idx = t + p * 256;
            int row = idx >> 5, c4 = idx & 31;
            float4 v = *(const float4*)(Ap + (size_t)(i0 + row) * CS + k0 + c4 * 4);
            float* dst = Asm + row * ALD + c4 * 4;
            dst[0] = wmma::__float_to_tf32(v.x);
            dst[1] = wmma::__float_to_tf32(v.y);
            dst[2] = wmma::__float_to_tf32(v.z);
            dst[3] = wmma::__float_to_tf32(v.w);
        }
        #pragma unroll
        for (int p = 0; p < 8; p++) {
            int idx = t + p * 256;
            int row = idx >> 4, c4 = idx & 15;
            float4 v = *(const float4*)(W + (size_t)(k0 + row) * CS + c0 + c4 * 4);
            float* dst = Wsm + row * WLD + c4 * 4;
            dst[0] = wmma::__float_to_tf32(v.x);
            dst[1] = wmma::__float_to_tf32(v.y);
            dst[2] = wmma::__float_to_tf32(v.z);
            dst[3] = wmma::__float_to_tf32(v.w);
        }
        __syncthreads();
        const float* abase = Asm + wr * 16 * ALD;
        const float* bbase = Wsm + wc * 32;
        #pragma unroll 8
        for (int k = 0; k < KCH / 8; k++) {
            wmma::load_matrix_sync(fa, abase + k * 8, ALD);
            wmma::load_matrix_sync(fb0, bbase + k * 8 * WLD, WLD);
            wmma::load_matrix_sync(fb1, bbase + k * 8 * WLD + 16, WLD);
            wmma::mma_sync(fc0, fa, fb0, fc0);
            wmma::mma_sync(fc1, fa, fb1, fc1);
        }
    }
    __syncthreads();
    wmma::store_matrix_sync(Csm + wr * 16 * WLD + wc * 32, fc0, WLD, wmma::mem_row_major);
    wmma::store_matrix_sync(Csm + wr * 16 * WLD + wc * 32 + 16, fc1, WLD, wmma::mem_row_major);
    __syncthreads();

    #pragma unroll
    for (int p = 0; p < 16; p++) {
        int idx = t + p * 256;
        int r = idx >> 6, c = idx & 63;
        float v = Csm[r * WLD + c];
        int gi = i0 + r, gc = c0 + c;
        if (mode == 0) {
            g_t[(size_t)z * (NSEQ * CS) + gi * CS + gc] = v;
        } else if (mode == 1) {
            int h = gc / DH, d = gc - h * DH;
            int oidx = h * (NSEQ * DH) + gi * DH + d;
            if (z == 0)      g_q[oidx] = (v + bias[gc]) * RSQRT_D;
            else if (z == 1) g_k[oidx] = v;
            else if (z == 2) g_v[oidx] = v;
            else             g_g[oidx] = sigm(v);
        } else if (mode == 2) {
            g_gate[gi * CS + gc] = sigm(v + bias[gc]);
        } else {
            outp[gi * CS + gc] = g_gate[gi * CS + gc] * v;
        }
    }
}

// =====================================================================
// AdaLN elementwise epilogue.
// =====================================================================
__global__ void __launch_bounds__(384) k_adaln_ep(const float* __restrict__ bs) {
    int i = blockIdx.x, c = threadIdx.x;
    int idx = i * CS + c;
    g_a[idx] = sigm(g_t[idx] + bs[c]) * g_aln[idx] + g_t[NSEQ * CS + idx];
}

// =====================================================================
// Kernel 3: pair bias (R11 ffma2 version). grid (8,1024), block 128,
// dyn smem ~74 KB.
// =====================================================================
#define PAIR_SMEM (128*132*4 + NH*64*8 + 2*NH*4)
__global__ void __launch_bounds__(128) k_pair(const float* __restrict__ z) {
    extern __shared__ float sm[];
    float* zs  = sm;
    u64*   wsm = (u64*)(sm + 128 * 132);
    float* WH  = (float*)(wsm + NH * 64);
    float* CH  = WH + NH;
    int t  = threadIdx.x;
    int i  = blockIdx.y;
    int j0 = blockIdx.x * 128;

    #pragma unroll
    for (int p = 0; p < 8; p++) wsm[t + p * 128] = g_wpk[t + p * 128];
    if (t < NH)            WH[t]      = g_WH[t];
    else if (t < 2 * NH)   CH[t - NH] = g_CH[t - NH];

    const float4* zg = (const float4*)(z + (size_t)i * (NSEQ * CZ) + (size_t)j0 * CZ);
    #pragma unroll
    for (int p = 0; p < 32; p++) {
        int f = t + p * 128;
        int jl = f >> 5, c4 = f & 31;
        *(float4*)&zs[jl * 132 + c4 * 4] = zg[(size_t)jl * 32 + c4];
    }
    __syncthreads();

    u64 acc[NH];
    #pragma unroll
    for (int h = 0; h < NH; h++) acc[h] = 0ull;
    u64 s2 = 0ull, q2 = 0ull;
    const float* zr = zs + t * 132;
    #pragma unroll 8
    for (int c4 = 0; c4 < 32; c4++) {
        float4 v = *(const float4*)&zr[c4 * 4];
        u64 v01 = pk2(v.x, v.y), v23 = pk2(v.z, v.w);
        s2 = fadd2(s2, fadd2(v01, v23));
        q2 = ffma2(v01, v01, q2);
        q2 = ffma2(v23, v23, q2);
        const u64* base = wsm + 2 * c4;
        #pragma unroll
        for (int h = 0; h < NH; h++) {
            ulonglong2 wv2 = *(const ulonglong2*)(base + h * 64);
            acc[h] = ffma2(v01, wv2.x, acc[h]);
            acc[h] = ffma2(v23, wv2.y, acc[h]);
        }
    }
    float sa, sb, qa, qb;
    upk2(s2, sa, sb); upk2(q2, qa, qb);
    float mean = (sa + sb) * (1.0f / CZ);
    float var  = (qa + qb) * (1.0f / CZ) - mean * mean;
    float rstd = rsqrtf(var + 1e-5f);
    int j = j0 + t;
    float* bo = g_bias + (size_t)i * NSEQ + j;
    #pragma unroll
    for (int h = 0; h < NH; h++) {
        float x0, x1; upk2(acc[h], x0, x1);
        bo[(size_t)h * NN] = ((x0 + x1) - mean * WH[h]) * rstd + CH[h];
    }
}

// =====================================================================
// Kernel 4: two-pass flash attention, PHASE-SPLIT K/V staging.
// One 104 KB buffer: stage K -> pass 1 (logits+max in regs) -> barrier
// -> stage V -> pass 2. Same LDS volume, but 2 blocks/SM (was 1) so
// 16 warps/SM hide the LDS/LDG latency. grid (64,16), block 256.
// =====================================================================
#define ATT_SMEM (NSEQ * 13 * 8)
__global__ void __launch_bounds__(256) k_attn() {
    extern __shared__ __align__(16) u64 sm8[];
    u64* buf = sm8;                       // K, then V
    int h  = blockIdx.y;
    int i0 = blockIdx.x * 16;
    int t  = threadIdx.x;
    int w = t >> 5, lane = t & 31;
    int iA = i0 + 2 * w, iB = iA + 1;

    // ---- stage K ----
    const float4* kg4 = (const float4*)(g_k + (size_t)h * NSEQ * DH);
    for (int idx = t; idx < NSEQ * 6; idx += 256) {
        int j = idx / 6, q4 = idx - j * 6;
        float4 kv = kg4[idx];
        buf[j * 13 + 2 * q4]     = pk2(kv.x, kv.y);
        buf[j * 13 + 2 * q4 + 1] = pk2(kv.z, kv.w);
    }

    u64 qpA[12], qpB[12];
    {
        const float4* qgA = (const float4*)(g_q + ((size_t)h * NSEQ + iA) * DH);
        const float4* qgB = (const float4*)(g_q + ((size_t)h * NSEQ + iB) * DH);
        #pragma unroll
        for (int p = 0; p < 6; p++) {
            float4 qa = qgA[p];
            qpA[2 * p]     = pk2(qa.x, qa.y);
            qpA[2 * p + 1] = pk2(qa.z, qa.w);
            float4 qb = qgB[p];
            qpB[2 * p]     = pk2(qb.x, qb.y);
            qpB[2 * p + 1] = pk2(qb.z, qb.w);
        }
    }
    const float* bpA = g_bias + (size_t)h * NN + (size_t)iA * NSEQ;
    const float* bpB = bpA + NSEQ;
    __syncthreads();

    // ---- pass 1: logits for both rows ----
    float lgsA[32], lgsB[32];
    float mxA = -1e30f, mxB = -1e30f;
    #pragma unroll
    for (int s = 0; s < 32; s++) {
        int j = s * 32 + lane;
        const u64* kr = buf + j * 13;
        u64 a0 = 0ull, a1 = 0ull, b0 = 0ull, b1 = 0ull;
        #pragma unroll
        for (int p = 0; p < 12; p += 2) {
            u64 k0 = kr[p], k1 = kr[p + 1];
            a0 = ffma2(qpA[p],     k0, a0);
            a1 = ffma2(qpA[p + 1], k1, a1);
            b0 = ffma2(qpB[p],     k0, b0);
            b1 = ffma2(qpB[p + 1], k1, b1);
        }
        float x0, x1, y0, y1;
        upk2(a0, x0, x1); upk2(a1, y0, y1);
        float lgA = bpA[j] + ((x0 + x1) + (y0 + y1));
        upk2(b0, x0, x1); upk2(b1, y0, y1);
        float lgB = bpB[j] + ((x0 + x1) + (y0 + y1));
        lgsA[s] = lgA; mxA = fmaxf(mxA, lgA);
        lgsB[s] = lgB; mxB = fmaxf(mxB, lgB);
    }
    #pragma unroll
    for (int off = 16; off > 0; off >>= 1) {
        mxA = fmaxf(mxA, __shfl_xor_sync(0xffffffffu, mxA, off));
        mxB = fmaxf(mxB, __shfl_xor_sync(0xffffffffu, mxB, off));
    }
    __syncthreads();                      // all warps done reading K

    // ---- stage V (overwrites K) ----
    const float4* vg4 = (const float4*)(g_v + (size_t)h * NSEQ * DH);
    for (int idx = t; idx < NSEQ * 6; idx += 256) {
        int j = idx / 6, q4 = idx - j * 6;
        float4 vv = vg4[idx];
        buf[j * 13 + 2 * q4]     = pk2(vv.x, vv.y);
        buf[j * 13 + 2 * q4 + 1] = pk2(vv.z, vv.w);
    }
    __syncthreads();

    // ---- pass 2: exp + PV ----
    float lA = 0.0f, lB = 0.0f;
    u64 oA[12], oB[12];
    #pragma unroll
    for (int p = 0; p < 12; p++) { oA[p] = 0ull; oB[p] = 0ull; }
    #pragma unroll
    for (int s = 0; s < 32; s++) {
        float pA = __expf(lgsA[s] - mxA);
        float pB = __expf(lgsB[s] - mxB);
        lA += pA; lB += pB;
        u64 ppA = pk2(pA, pA), ppB = pk2(pB, pB);
        const u64* vr = buf + (s * 32 + lane) * 13;
        #pragma unroll
        for (int q = 0; q < 12; q++) {
            u64 vv = vr[q];
            oA[q] = ffma2(ppA, vv, oA[q]);
            oB[q] = ffma2(ppB, vv, oB[q]);
        }
    }
    #pragma unroll
    for (int off = 16; off > 0; off >>= 1) {
        lA += __shfl_xor_sync(0xffffffffu, lA, off);
        lB += __shfl_xor_sync(0xffffffffu, lB, off);
    }
    float fA[DH], fB[DH];
    #pragma unroll
    for (int q = 0; q < 12; q++) {
        upk2(oA[q], fA[2 * q], fA[2 * q + 1]);
        upk2(oB[q], fB[2 * q], fB[2 * q + 1]);
    }
    #pragma unroll
    for (int d = 0; d < DH; d++) {
        #pragma unroll
        for (int off = 16; off > 0; off >>= 1) {
            fA[d] += __shfl_xor_sync(0xffffffffu, fA[d], off);
            fB[d] += __shfl_xor_sync(0xffffffffu, fB[d], off);
        }
    }
    if (lane == 0) {
        float invA = 1.0f / lA;
        const float* ggA = g_g + ((size_t)h * NSEQ + iA) * DH;
        float* opA = g_o + (size_t)iA * HC + h * DH;
        #pragma unroll
        for (int d = 0; d < DH; d++) opA[d] = fA[d] * invA * ggA[d];
        float invB = 1.0f / lB;
        const float* ggB = g_g + ((size_t)h * NSEQ + iB) * DH;
        float* opB = g_o + (size_t)iB * HC + h * DH;
        #pragma unroll
        for (int d = 0; d < DH; d++) opB[d] = fB[d] * invB * ggB[d];
    }
}

// =====================================================================
extern "C" void kernel_launch(void* const* d_in, const int* in_sizes, int n_in,
                              void* d_out, int out_size) {
    const float* a_i   = (const float*)d_in[0];
    const float* s_i   = (const float*)d_in[1];
    const float* z     = (const float*)d_in[2];
    const float* lns_w = (const float*)d_in[3];
    const float* aws   = (const float*)d_in[4];
    const float* abs_  = (const float*)d_in[5];
    const float* awns  = (const float*)d_in[6];
    const float* wq    = (const float*)d_in[7];
    const float* bq    = (const float*)d_in[8];
    const float* wk    = (const float*)d_in[9];
    const float* wv    = (const float*)d_in[10];
    const float* lnb_w = (const float*)d_in[11];
    const float* lnb_b = (const float*)d_in[12];
    const float* wb    = (const float*)d_in[13];
    const float* wg    = (const float*)d_in[14];
    const float* wo    = (const float*)d_in[15];
    const float* ws2   = (const float*)d_in[16];
    const float* bs2   = (const float*)d_in[17];
    float* out = (float*)d_out;

    static cudaStream_t sA = 0, sB = 0;
    static cudaEvent_t evF = 0, evA = 0, evB = 0;
    static int inited = 0;
    if (!inited) {
        cudaStreamCreateWithFlags(&sA, cudaStreamNonBlocking);
        cudaStreamCreateWithFlags(&sB, cudaStreamNonBlocking);
        cudaEventCreateWithFlags(&evF, cudaEventDisableTiming);
        cudaEventCreateWithFlags(&evA, cudaEventDisableTiming);
        cudaEventCreateWithFlags(&evB, cudaEventDisableTiming);
        cudaFuncSetAttribute(k_pair, cudaFuncAttributeMaxDynamicSharedMemorySize, PAIR_SMEM);
        cudaFuncSetAttribute(k_attn, cudaFuncAttributeMaxDynamicSharedMemorySize, ATT_SMEM);
        cudaFuncSetAttribute(k_gemm, cudaFuncAttributeMaxDynamicSharedMemorySize, GEMM_SMEM);
        inited = 1;
    }

    // fork
    cudaEventRecord(evF, 0);
    cudaStreamWaitEvent(sA, evF, 0);
    cudaStreamWaitEvent(sB, evF, 0);

    // stream A: pair-bias path (launched first; gemm blocks co-reside)
    k_prep<<<1, 128, 0, sA>>>(lnb_w, lnb_b, wb);
    k_pair<<<dim3(8, NSEQ), 128, PAIR_SMEM, sA>>>(z);

    // stream B: final conditioning gate
    k_gemm<<<dim3(6, 16, 1), 256, GEMM_SMEM, sB>>>(s_i, ws2, nullptr, nullptr, nullptr,
                                                   bs2, nullptr, 2, 2);

    // default stream: LN -> AdaLN -> QKV/gate chain
    k_ln<<<NSEQ, CS>>>(a_i, s_i, lns_w);
    k_gemm<<<dim3(6, 16, 2), 256, GEMM_SMEM>>>(nullptr, aws, awns, nullptr, nullptr,
                                               nullptr, nullptr, 0, 0);
    k_adaln_ep<<<NSEQ, CS>>>(abs_);
    k_gemm<<<dim3(6, 16, 4), 256, GEMM_SMEM>>>(nullptr, wq, wk, wv, wg,
                                               bq, nullptr, 1, 1);

    // join
    cudaEventRecord(evA, sA);
    cudaEventRecord(evB, sB);
    cudaStreamWaitEvent(0, evA, 0);
    cudaStreamWaitEvent(0, evB, 0);

    k_attn<<<dim3(64, 16), 256, ATT_SMEM>>>();
    k_gemm<<<dim3(6, 16, 1), 256, GEMM_SMEM>>>(nullptr, wo, nullptr, nullptr, nullptr,
                                               nullptr, out, 3, 3);
}